// round 15
// baseline (speedup 1.0000x reference)
#include <cuda_runtime.h>
#include <cuda_fp16.h>
#include <math.h>
#include <stdint.h>

#define SLEN 1024
#define BSZ  32
#define INDIM 512
#define H 8
#define D 64
#define NQKVB 1544
#define NQKVB_PAD 1664
#define MROWS 32768
#define NBH 256
#define NC 16
#define LN_EPS 1e-5f
#define PADH 72
#define PADF 65
#define TILE_H 4608

__device__ __half g_hh[(size_t)MROWS * INDIM];
__device__ __half g_qkvbh[(size_t)MROWS * NQKVB_PAD];   // permuted: q|k|v|beta|pad
__device__ __half g_oh[(size_t)MROWS * INDIM];
__device__ __half g_wslowT[(size_t)NQKVB_PAD * INDIM];
__device__ __half g_woutT[(size_t)INDIM * INDIM];

#define MMA16816(d, a0, a1, a2, a3, b0, b1)                                   \
    asm volatile("mma.sync.aligned.m16n8k16.row.col.f32.f16.f16.f32 "         \
        "{%0,%1,%2,%3},{%4,%5,%6,%7},{%8,%9},{%0,%1,%2,%3};"                   \
        : "+f"((d)[0]), "+f"((d)[1]), "+f"((d)[2]), "+f"((d)[3])               \
        : "r"(a0), "r"(a1), "r"(a2), "r"(a3), "r"(b0), "r"(b1))

#define LDSM4(r0, r1, r2, r3, a)                                              \
    asm volatile("ldmatrix.sync.aligned.m8n8.x4.shared.b16 {%0,%1,%2,%3}, [%4];" \
        : "=r"(r0), "=r"(r1), "=r"(r2), "=r"(r3) : "r"(a))

#define LDSM4T(r0, r1, r2, r3, a)                                             \
    asm volatile("ldmatrix.sync.aligned.m8n8.x4.trans.shared.b16 {%0,%1,%2,%3}, [%4];" \
        : "=r"(r0), "=r"(r1), "=r"(r2), "=r"(r3) : "r"(a))

__device__ __forceinline__ uint32_t smem_u32(const void* p) {
    uint32_t a;
    asm("{ .reg .u64 t; cvta.to.shared.u64 t, %1; cvt.u32.u64 %0, t; }" : "=r"(a) : "l"(p));
    return a;
}

// acc[nf*4+q] += A'[m][k] * B'[k][n]  over k=0..63, tiles stride PADH.
// TA=0: A row-major [m][k];  TA=1: logical A = src^T (src row-major [k][m]).
// TB=0: B given as [n][k] (i.e. B^T rows);  TB=1: B row-major [k][n].
template<int TA, int TB>
__device__ __forceinline__ void wgemmT(const __half* At, const __half* Bt,
                                       float acc[16], int m0, int n0, int lane)
{
    const int l7 = lane & 7, b3 = (lane >> 3) & 1, b4 = (lane >> 4) & 1;
    #pragma unroll
    for (int kb = 0; kb < 64; kb += 16) {
        uint32_t a0, a1, a2, a3;
        if (!TA) {
            LDSM4(a0, a1, a2, a3, smem_u32(At + (m0 + l7 + b3 * 8) * PADH + kb + b4 * 8));
        } else {
            LDSM4T(a0, a1, a2, a3, smem_u32(At + (kb + l7 + b4 * 8) * PADH + m0 + b3 * 8));
        }
        #pragma unroll
        for (int i2 = 0; i2 < 2; i2++) {
            const int nb = n0 + i2 * 16;
            uint32_t b0, b1, b2, b3r;
            if (!TB) {
                LDSM4(b0, b1, b2, b3r, smem_u32(Bt + (nb + l7 + b4 * 8) * PADH + kb + b3 * 8));
            } else {
                LDSM4T(b0, b1, b2, b3r, smem_u32(Bt + (kb + l7 + b3 * 8) * PADH + nb + b4 * 8));
            }
            MMA16816(&acc[(2 * i2) * 4], a0, a1, a2, a3, b0, b1);
            MMA16816(&acc[(2 * i2 + 1) * 4], a0, a1, a2, a3, b2, b3r);
        }
    }
}

#define CP_COMMIT() asm volatile("cp.async.commit_group;")
#define CP_WAIT(n)  asm volatile("cp.async.wait_group %0;" :: "n"(n))

// ---------------- weight transpose (+optional head-split permutation) ----------------
__global__ __launch_bounds__(256)
void transpose_pad_kernel(const float* __restrict__ src, __half* __restrict__ dst,
                          int K, int N, int Npad, int permute)
{
    __shared__ float tile[32][33];
    const int n0 = blockIdx.x * 32, k0 = blockIdx.y * 32;
    const int tx = threadIdx.x & 31, ty = threadIdx.x >> 5;
    #pragma unroll
    for (int i = ty; i < 32; i += 8) {
        const int n = n0 + tx;
        tile[i][tx] = (n < N) ? src[(size_t)(k0 + i) * N + n] : 0.f;
    }
    __syncthreads();
    #pragma unroll
    for (int i = ty; i < 32; i += 8) {
        int n = n0 + i;
        if (n < Npad) {
            int nd = n;
            if (permute && n < N) {
                const int h = n / 193, r = n % 193;
                nd = (r < 64)  ? h * 64 + r
                   : (r < 128) ? 512 + h * 64 + (r - 64)
                   : (r < 192) ? 1024 + h * 64 + (r - 128)
                               : 1536 + h;
            }
            dst[(size_t)nd * K + k0 + tx] = __float2half(tile[tx][i]);
        }
    }
}

// ---------------- LayerNorm, warp-per-row ----------------
__global__ __launch_bounds__(256)
void ln_kernel(const float* __restrict__ x, const float* __restrict__ gamma,
               const float* __restrict__ beta)
{
    const int w = threadIdx.x >> 5, lane = threadIdx.x & 31;
    const int r = blockIdx.x * 8 + w;
    const float* xr = x + (size_t)r * INDIM;

    float4 v[4];
    float s = 0.f, ss = 0.f;
    #pragma unroll
    for (int i = 0; i < 4; i++) {
        v[i] = *(const float4*)(xr + lane * 4 + i * 128);
        s  += v[i].x + v[i].y + v[i].z + v[i].w;
        ss += v[i].x * v[i].x + v[i].y * v[i].y + v[i].z * v[i].z + v[i].w * v[i].w;
    }
    #pragma unroll
    for (int o = 16; o; o >>= 1) {
        s  += __shfl_xor_sync(~0u, s, o);
        ss += __shfl_xor_sync(~0u, ss, o);
    }
    const float mu = s * (1.f / INDIM);
    const float inv = rsqrtf(ss * (1.f / INDIM) - mu * mu + LN_EPS);

    __half* hr = g_hh + (size_t)r * INDIM;
    #pragma unroll
    for (int i = 0; i < 4; i++) {
        const int c0 = lane * 4 + i * 128;
        const float4 gm = *(const float4*)(gamma + c0);
        const float4 bt = *(const float4*)(beta + c0);
        __half2 h0 = __floats2half2_rn((v[i].x - mu) * inv * gm.x + bt.x,
                                       (v[i].y - mu) * inv * gm.y + bt.y);
        __half2 h1 = __floats2half2_rn((v[i].z - mu) * inv * gm.z + bt.z,
                                       (v[i].w - mu) * inv * gm.w + bt.w);
        *(uint2*)(hr + c0) = make_uint2(*(uint32_t*)&h0, *(uint32_t*)&h1);
    }
}

// ---------------- big GEMM (occ 2, 128-reg budget) ----------------
#define BK 32
#define KT (INDIM / BK)
#define ROWP 40
#define STG (128 * ROWP)
#define GEMM_SMEM (3 * 2 * STG * 2)

__device__ __forceinline__ void load_stage(__half* sm, const __half* __restrict__ g,
                                           int row0, int k0, int tid)
{
    #pragma unroll
    for (int i = 0; i < 2; i++) {
        const int idx = tid + i * 256;
        const int row = idx >> 2, ch = (idx & 3) << 3;
        uint32_t dst;
        asm("{ .reg .u64 t; cvta.to.shared.u64 t, %1; cvt.u32.u64 %0, t; }"
            : "=r"(dst) : "l"(sm + row * ROWP + ch));
        asm volatile("cp.async.cg.shared.global [%0], [%1], 16;"
                     :: "r"(dst), "l"(g + (size_t)(row0 + row) * INDIM + (k0 + ch)));
    }
}

__global__ __launch_bounds__(256, 2)
void gemm_hmma_kernel(const __half* __restrict__ A, const __half* __restrict__ Bt,
                      float* __restrict__ C, __half* __restrict__ Ch,
                      const float* __restrict__ Res, int Ncols)
{
    extern __shared__ __half sm[];
    const uint32_t smb = smem_u32(sm);
    const int tid = threadIdx.x, wid = tid >> 5, lane = tid & 31;
    const int bm = blockIdx.y * 128, bn = blockIdx.x * 128;
    const int wm = (wid >> 2) * 64, wn = (wid & 3) * 32;
    const int g = lane >> 2, c = lane & 3;
    const int rA = (lane & 7) + ((lane >> 3) & 1) * 8;
    const int cA = ((lane >> 4) & 1) * 8;
    const int rB = (lane & 7) + ((lane >> 4) & 1) * 8;
    const int cB = ((lane >> 3) & 1) * 8;

    float acc[4][4][4];
    #pragma unroll
    for (int i = 0; i < 4; i++)
        #pragma unroll
        for (int j = 0; j < 4; j++)
            #pragma unroll
            for (int r = 0; r < 4; r++) acc[i][j][r] = 0.f;

    load_stage(sm, A, bm, 0, tid); load_stage(sm + 3 * STG, Bt, bn, 0, tid); CP_COMMIT();
    load_stage(sm + STG, A, bm, BK, tid); load_stage(sm + 4 * STG, Bt, bn, BK, tid); CP_COMMIT();

    for (int kt = 0; kt < KT; ++kt) {
        CP_WAIT(1);
        __syncthreads();
        if (kt + 2 < KT) {
            const int ps = (kt + 2) % 3;
            load_stage(sm + ps * STG, A, bm, (kt + 2) * BK, tid);
            load_stage(sm + (3 + ps) * STG, Bt, bn, (kt + 2) * BK, tid);
        }
        CP_COMMIT();
        const uint32_t sau = smb + ((kt % 3) * STG) * 2;
        const uint32_t sbu = smb + ((3 + kt % 3) * STG) * 2;
        #pragma unroll
        for (int ks = 0; ks < 2; ks++) {
            const int kb = ks * 16;
            uint32_t af[4][4], bf[4][2];
            #pragma unroll
            for (int im = 0; im < 4; im++)
                LDSM4(af[im][0], af[im][1], af[im][2], af[im][3],
                      sau + ((wm + im * 16 + rA) * ROWP + kb + cA) * 2);
            #pragma unroll
            for (int i2 = 0; i2 < 2; i2++)
                LDSM4(bf[2 * i2][0], bf[2 * i2][1], bf[2 * i2 + 1][0], bf[2 * i2 + 1][1],
                      sbu + ((wn + i2 * 16 + rB) * ROWP + kb + cB) * 2);
            #pragma unroll
            for (int im = 0; im < 4; im++)
                #pragma unroll
                for (int in = 0; in < 4; in++)
                    MMA16816(acc[im][in], af[im][0], af[im][1], af[im][2], af[im][3],
                             bf[in][0], bf[in][1]);
        }
    }

    #pragma unroll
    for (int im = 0; im < 4; im++)
        #pragma unroll
        for (int in = 0; in < 4; in++) {
            const int col = bn + wn + in * 8 + 2 * c;
            if (col < Ncols) {
                const int r0 = bm + wm + im * 16 + g;
                if (Ch) {
                    *(__half2*)&Ch[(size_t)r0 * Ncols + col] =
                        __floats2half2_rn(acc[im][in][0], acc[im][in][1]);
                    *(__half2*)&Ch[(size_t)(r0 + 8) * Ncols + col] =
                        __floats2half2_rn(acc[im][in][2], acc[im][in][3]);
                } else {
                    float2 v0 = make_float2(acc[im][in][0], acc[im][in][1]);
                    float2 v1 = make_float2(acc[im][in][2], acc[im][in][3]);
                    const float2 a0 = *(const float2*)(Res + (size_t)r0 * Ncols + col);
                    const float2 a1 = *(const float2*)(Res + (size_t)(r0 + 8) * Ncols + col);
                    v0.x += a0.x; v0.y += a0.y; v1.x += a1.x; v1.y += a1.y;
                    *(float2*)(C + (size_t)r0 * Ncols + col) = v0;
                    *(float2*)(C + (size_t)(r0 + 8) * Ncols + col) = v1;
                }
            }
        }
}

// ---------------- fused scan: KW/QW overlapped with the solve (256 CTAs) ----------------
// Tiles: sK | sQ | sV -> P | sU | sG -> O stage | sS | sWh
#define FUSED_SMEM (7 * TILE_H * 2 + (64 * PADF + 64 * 68 + 64) * 4)

__global__ __launch_bounds__(256, 2)
void fused_scan_kernel()
{
    extern __shared__ char smraw[];
    __half* sK   = (__half*)smraw;
    __half* sQ   = sK  + TILE_H;
    __half* sV   = sQ  + TILE_H;        // V -> P in place
    __half* sU   = sV  + TILE_H;
    __half* sG   = sU  + TILE_H;        // G -> O staging
    __half* sS   = sG  + TILE_H;
    __half* sWh  = sS  + TILE_H;
    float*  sA   = (float*)(sWh + TILE_H);
    float*  sW   = sA + 64 * PADF;
    float*  sbt  = sW + 64 * 68;

    const int bh = blockIdx.x;
    const int b = bh >> 3, hh = bh & 7;
    const int tid = threadIdx.x, wid = tid >> 5, lane = tid & 31;
    const int g = lane >> 2, cq = lane & 3;
    const int tt = tid >> 2, qt = tid & 3;
    const int m0 = (wid & 3) * 16, n0 = (wid >> 2) * 32;
    const int seg = hh * 64 + qt * 16;

    #pragma unroll
    for (int i = 0; i < 16; i++) {
        const int e = tid * 16 + i;
        const int r = e >> 6, c2 = e & 63;
        sW[r * 68 + c2] = 0.f;
        sWh[r * PADH + c2] = __float2half(0.f);
    }
    __syncthreads();

    // register prefetch (chunk 0)
    uint4 pq0, pq1, pk0, pk1, pv0, pv1;
    float pbeta = 0.f;
    {
        const __half* rowp = g_qkvbh + (size_t)(tt * BSZ + b) * NQKVB_PAD;
        pq0 = *(const uint4*)(rowp + seg);        pq1 = *(const uint4*)(rowp + seg + 8);
        pk0 = *(const uint4*)(rowp + 512 + seg);  pk1 = *(const uint4*)(rowp + 512 + seg + 8);
        pv0 = *(const uint4*)(rowp + 1024 + seg); pv1 = *(const uint4*)(rowp + 1024 + seg + 8);
        if (qt == 0) pbeta = __half2float(rowp[1536 + hh]);
    }

    for (int cch = 0; cch < NC; cch++) {
        const int t0 = cch * 64;

        // ---- (a) act ----
        {
            if (qt == 0) sbt[tt] = 1.f / (1.f + __expf(-pbeta));
            __half hq[16], hk[16];
            *(uint4*)&hq[0] = pq0; *(uint4*)&hq[8] = pq1;
            *(uint4*)&hk[0] = pk0; *(uint4*)&hk[8] = pk1;

            float qv[16], kv[16];
            float sq = 0.f, sk_ = 0.f;
            #pragma unroll
            for (int i = 0; i < 16; i++) {
                float xq = __half2float(hq[i]);
                float xk = __half2float(hk[i]);
                qv[i] = xq > 0.f ? xq + 1.f : __expf(xq);
                kv[i] = xk > 0.f ? xk + 1.f : __expf(xk);
                sq += qv[i]; sk_ += kv[i];
            }
            sq  += __shfl_xor_sync(~0u, sq, 1);  sq  += __shfl_xor_sync(~0u, sq, 2);
            sk_ += __shfl_xor_sync(~0u, sk_, 1); sk_ += __shfl_xor_sync(~0u, sk_, 2);
            const float iq = 1.f / sq, ik = 1.f / sk_;
            __half outq[16], outk[16];
            #pragma unroll
            for (int i = 0; i < 16; i++) {
                outq[i] = __float2half(qv[i] * iq);
                outk[i] = __float2half(kv[i] * ik);
            }
            const int cb = qt * 16;
            *(uint4*)&sQ[tt * PADH + cb]     = *(uint4*)&outq[0];
            *(uint4*)&sQ[tt * PADH + cb + 8] = *(uint4*)&outq[8];
            *(uint4*)&sK[tt * PADH + cb]     = *(uint4*)&outk[0];
            *(uint4*)&sK[tt * PADH + cb + 8] = *(uint4*)&outk[8];
            *(uint4*)&sV[tt * PADH + cb]     = pv0;
            *(uint4*)&sV[tt * PADH + cb + 8] = pv1;
        }
        __syncthreads();   // (a)

        // prefetch next chunk
        if (cch + 1 < NC) {
            const __half* rowp = g_qkvbh + (size_t)(((cch + 1) * 64 + tt) * BSZ + b) * NQKVB_PAD;
            pq0 = *(const uint4*)(rowp + seg);        pq1 = *(const uint4*)(rowp + seg + 8);
            pk0 = *(const uint4*)(rowp + 512 + seg);  pk1 = *(const uint4*)(rowp + 512 + seg + 8);
            pv0 = *(const uint4*)(rowp + 1024 + seg); pv1 = *(const uint4*)(rowp + 1024 + seg + 8);
            if (qt == 0) pbeta = __half2float(rowp[1536 + hh]);
        }

        // ---- (b) A = K·K^T, S = Q·K^T only ----
        {
            float aA[16], aS[16];
            #pragma unroll
            for (int i = 0; i < 16; i++) { aA[i] = 0.f; aS[i] = 0.f; }
            wgemmT<0, 0>(sK, sK, aA, m0, n0, lane);
            wgemmT<0, 0>(sQ, sK, aS, m0, n0, lane);
            #pragma unroll
            for (int nf = 0; nf < 4; nf++)
                #pragma unroll
                for (int qq = 0; qq < 2; qq++) {
                    const int t = m0 + g + qq * 8;
                    const int s0 = n0 + nf * 8 + 2 * cq;
                    const float a0v = aA[nf * 4 + qq * 2], a1v = aA[nf * 4 + qq * 2 + 1];
                    sA[t * PADF + s0]     = (s0 < t)     ? sbt[t] * a0v : 0.f;
                    sA[t * PADF + s0 + 1] = (s0 + 1 < t) ? sbt[t] * a1v : 0.f;
                    const float s0v = (s0 <= t)     ? aS[nf * 4 + qq * 2]     : 0.f;
                    const float s1v = (s0 + 1 <= t) ? aS[nf * 4 + qq * 2 + 1] : 0.f;
                    *(__half2*)&sS[t * PADH + s0] = __floats2half2_rn(s0v, s1v);
                }
        }
        __syncthreads();   // (b)

        // ---- (c) kw = K·W^T, O1 = Q·W^T (MMA) overlapped with the solve (shfl chain) ----
        float oa[16];
        {
            float akw[16];
            #pragma unroll
            for (int i = 0; i < 16; i++) { akw[i] = 0.f; oa[i] = 0.f; }
            wgemmT<0, 0>(sK, sWh, akw, m0, n0, lane);
            wgemmT<0, 0>(sQ, sWh, oa, m0, n0, lane);
            // P = V - kw, in place (element-owner exclusive)
            #pragma unroll
            for (int nf = 0; nf < 4; nf++)
                #pragma unroll
                for (int qq = 0; qq < 2; qq++) {
                    const int t = m0 + g + qq * 8;
                    const int s0 = n0 + nf * 8 + 2 * cq;
                    const __half2 vv = *(const __half2*)&sV[t * PADH + s0];
                    *(__half2*)&sV[t * PADH + s0] = __floats2half2_rn(
                        __half2float(vv.x) - akw[nf * 4 + qq * 2],
                        __half2float(vv.y) - akw[nf * 4 + qq * 2 + 1]);
                }
        }
        // solve (warp-autonomous quad-parallel; overlaps with other warps' MMAs)
        {
            const int col = tid >> 2;
            const int qr  = tid & 3;
            float m[16];
            #pragma unroll
            for (int i = 0; i < 16; i++) m[i] = (16 * qr + i == col) ? 1.f : 0.f;
            for (int p = 0; p < 4; p++) {
                #pragma unroll
                for (int si = 0; si < 16; si++) {
                    const int s = 16 * p + si;
                    const float ms = __shfl_sync(0xFFFFFFFFu, m[si], p, 4);
                    if (ms != 0.f && qr >= p && s < 63) {
                        const int lo = (qr == p) ? si : -1;
                        #pragma unroll
                        for (int i = 0; i < 16; i++)
                            if (i > lo)
                                m[i] -= sA[(16 * qr + i) * PADF + s] * ms;
                    }
                }
            }
            const float bc = sbt[col];
            #pragma unroll
            for (int i = 0; i < 16; i++)
                sG[(16 * qr + i) * PADH + col] = __float2half(m[i] * bc);
        }
        __syncthreads();   // (c)

        // ---- (d) U = G @ P ----
        {
            float aU[16];
            #pragma unroll
            for (int i = 0; i < 16; i++) aU[i] = 0.f;
            wgemmT<0, 1>(sG, sV, aU, m0, n0, lane);
            #pragma unroll
            for (int nf = 0; nf < 4; nf++)
                #pragma unroll
                for (int qq = 0; qq < 2; qq++) {
                    const int t = m0 + g + qq * 8;
                    const int col = n0 + nf * 8 + 2 * cq;
                    *(__half2*)&sU[t * PADH + col] =
                        __floats2half2_rn(aU[nf * 4 + qq * 2], aU[nf * 4 + qq * 2 + 1]);
                }
        }
        __syncthreads();   // (d)

        // ---- (e) O2 = S @ U; stage O in sG; W += U^T @ K ----
        wgemmT<0, 1>(sS, sU, oa, m0, n0, lane);
        #pragma unroll
        for (int nf = 0; nf < 4; nf++)
            #pragma unroll
            for (int qq = 0; qq < 2; qq++) {
                const int t = m0 + g + qq * 8;
                const int col = n0 + nf * 8 + 2 * cq;
                *(__half2*)&sG[t * PADH + col] =
                    __floats2half2_rn(oa[nf * 4 + qq * 2], oa[nf * 4 + qq * 2 + 1]);
            }
        {
            float wa[16];
            #pragma unroll
            for (int i = 0; i < 16; i++) wa[i] = 0.f;
            wgemmT<1, 1>(sU, sK, wa, m0, n0, lane);
            #pragma unroll
            for (int nf = 0; nf < 4; nf++)
                #pragma unroll
                for (int qq = 0; qq < 2; qq++) {
                    const int i = m0 + g + qq * 8;
                    const int j0 = n0 + nf * 8 + 2 * cq;
                    const float w0 = sW[i * 68 + j0]     + wa[nf * 4 + qq * 2];
                    const float w1 = sW[i * 68 + j0 + 1] + wa[nf * 4 + qq * 2 + 1];
                    *(float2*)&sW[i * 68 + j0] = make_float2(w0, w1);
                    *(__half2*)&sWh[i * PADH + j0] = __floats2half2_rn(w0, w1);
                }
        }
        __syncthreads();   // (e)

        // ---- coalesced O store ----
        {
            const int qseg = qt * 16;
            const uint4* src = (const uint4*)&sG[tt * PADH + qseg];
            uint4* dst = (uint4*)&g_oh[(size_t)((t0 + tt) * BSZ + b) * INDIM + hh * 64 + qseg];
            dst[0] = src[0];
            dst[1] = src[1];
        }
    }
}

// ---------------- launch ----------------
extern "C" void kernel_launch(void* const* d_in, const int* in_sizes, int n_in,
                              void* d_out, int out_size)
{
    const float* x      = (const float*)d_in[0];
    const float* gamma  = (const float*)d_in[1];
    const float* beta   = (const float*)d_in[2];
    const float* w_slow = (const float*)d_in[3];
    const float* w_out  = (const float*)d_in[4];
    float* out = (float*)d_out;

    static bool attr_set = false;
    if (!attr_set) {
        cudaFuncSetAttribute(gemm_hmma_kernel, cudaFuncAttributeMaxDynamicSharedMemorySize, GEMM_SMEM);
        cudaFuncSetAttribute(fused_scan_kernel, cudaFuncAttributeMaxDynamicSharedMemorySize, FUSED_SMEM);
        attr_set = true;
    }

    __half* wslowT; cudaGetSymbolAddress((void**)&wslowT, g_wslowT);
    __half* woutT;  cudaGetSymbolAddress((void**)&woutT,  g_woutT);
    __half* hbuf;   cudaGetSymbolAddress((void**)&hbuf,   g_hh);
    __half* qkvbh;  cudaGetSymbolAddress((void**)&qkvbh,  g_qkvbh);
    __half* obuf;   cudaGetSymbolAddress((void**)&obuf,   g_oh);

    {
        dim3 blk(256);
        dim3 g1(NQKVB_PAD / 32, INDIM / 32);
        transpose_pad_kernel<<<g1, blk>>>(w_slow, wslowT, INDIM, NQKVB, NQKVB_PAD, 1);
        dim3 g2(INDIM / 32, INDIM / 32);
        transpose_pad_kernel<<<g2, blk>>>(w_out, woutT, INDIM, INDIM, INDIM, 0);
    }
    ln_kernel<<<MROWS / 8, 256>>>(x, gamma, beta);
    {
        dim3 grid(NQKVB_PAD / 128, MROWS / 128);
        gemm_hmma_kernel<<<grid, 256, GEMM_SMEM>>>(hbuf, wslowT, nullptr, qkvbh, nullptr, NQKVB_PAD);
    }
    fused_scan_kernel<<<NBH, 256, FUSED_SMEM>>>();
    {
        dim3 grid(INDIM / 128, MROWS / 128);
        gemm_hmma_kernel<<<grid, 256, GEMM_SMEM>>>(obuf, woutT, out, nullptr, x, INDIM);
    }
}

// round 16
// speedup vs baseline: 1.0560x; 1.0560x over previous
#include <cuda_runtime.h>
#include <cuda_fp16.h>
#include <math.h>
#include <stdint.h>

#define SLEN 1024
#define BSZ  32
#define INDIM 512
#define H 8
#define D 64
#define NQKVB 1544
#define NQKVB_PAD 1664
#define MROWS 32768
#define NBH 256
#define NC 16
#define LN_EPS 1e-5f
#define PADH 72
#define PADF 68
#define TILE_H 4608

__device__ __half g_hh[(size_t)MROWS * INDIM];
__device__ __half g_qkvbh[(size_t)MROWS * NQKVB_PAD];
__device__ __half g_oh[(size_t)MROWS * INDIM];
__device__ __half g_wslowT[(size_t)NQKVB_PAD * INDIM];
__device__ __half g_woutT[(size_t)INDIM * INDIM];

#define MMA16816(d, a0, a1, a2, a3, b0, b1)                                   \
    asm volatile("mma.sync.aligned.m16n8k16.row.col.f32.f16.f16.f32 "         \
        "{%0,%1,%2,%3},{%4,%5,%6,%7},{%8,%9},{%0,%1,%2,%3};"                   \
        : "+f"((d)[0]), "+f"((d)[1]), "+f"((d)[2]), "+f"((d)[3])               \
        : "r"(a0), "r"(a1), "r"(a2), "r"(a3), "r"(b0), "r"(b1))

#define LDSM4(r0, r1, r2, r3, a)                                              \
    asm volatile("ldmatrix.sync.aligned.m8n8.x4.shared.b16 {%0,%1,%2,%3}, [%4];" \
        : "=r"(r0), "=r"(r1), "=r"(r2), "=r"(r3) : "r"(a))

#define LDSM4T(r0, r1, r2, r3, a)                                             \
    asm volatile("ldmatrix.sync.aligned.m8n8.x4.trans.shared.b16 {%0,%1,%2,%3}, [%4];" \
        : "=r"(r0), "=r"(r1), "=r"(r2), "=r"(r3) : "r"(a))

__device__ __forceinline__ uint32_t smem_u32(const void* p) {
    uint32_t a;
    asm("{ .reg .u64 t; cvta.to.shared.u64 t, %1; cvt.u32.u64 %0, t; }" : "=r"(a) : "l"(p));
    return a;
}

// acc += A'[m][k] * B'[k][n], k=0..63, stride PADH. TA=1: A = src^T. TB=0: B as [n][k]; TB=1: B as [k][n].
template<int TA, int TB>
__device__ __forceinline__ void wgemmT(const __half* At, const __half* Bt,
                                       float acc[16], int m0, int n0, int lane)
{
    const int l7 = lane & 7, b3 = (lane >> 3) & 1, b4 = (lane >> 4) & 1;
    #pragma unroll
    for (int kb = 0; kb < 64; kb += 16) {
        uint32_t a0, a1, a2, a3;
        if (!TA) {
            LDSM4(a0, a1, a2, a3, smem_u32(At + (m0 + l7 + b3 * 8) * PADH + kb + b4 * 8));
        } else {
            LDSM4T(a0, a1, a2, a3, smem_u32(At + (kb + l7 + b4 * 8) * PADH + m0 + b3 * 8));
        }
        #pragma unroll
        for (int i2 = 0; i2 < 2; i2++) {
            const int nb = n0 + i2 * 16;
            uint32_t b0, b1, b2, b3r;
            if (!TB) {
                LDSM4(b0, b1, b2, b3r, smem_u32(Bt + (nb + l7 + b4 * 8) * PADH + kb + b3 * 8));
            } else {
                LDSM4T(b0, b1, b2, b3r, smem_u32(Bt + (kb + l7 + b3 * 8) * PADH + nb + b4 * 8));
            }
            MMA16816(&acc[(2 * i2) * 4], a0, a1, a2, a3, b0, b1);
            MMA16816(&acc[(2 * i2 + 1) * 4], a0, a1, a2, a3, b2, b3r);
        }
    }
}

#define CP_COMMIT() asm volatile("cp.async.commit_group;")
#define CP_WAIT(n)  asm volatile("cp.async.wait_group %0;" :: "n"(n))

// ---------------- weight transpose ----------------
__global__ __launch_bounds__(256)
void transpose_pad_kernel(const float* __restrict__ src, __half* __restrict__ dst,
                          int K, int N, int Npad, int permute)
{
    __shared__ float tile[32][33];
    const int n0 = blockIdx.x * 32, k0 = blockIdx.y * 32;
    const int tx = threadIdx.x & 31, ty = threadIdx.x >> 5;
    #pragma unroll
    for (int i = ty; i < 32; i += 8) {
        const int n = n0 + tx;
        tile[i][tx] = (n < N) ? src[(size_t)(k0 + i) * N + n] : 0.f;
    }
    __syncthreads();
    #pragma unroll
    for (int i = ty; i < 32; i += 8) {
        int n = n0 + i;
        if (n < Npad) {
            int nd = n;
            if (permute && n < N) {
                const int h = n / 193, r = n % 193;
                nd = (r < 64)  ? h * 64 + r
                   : (r < 128) ? 512 + h * 64 + (r - 64)
                   : (r < 192) ? 1024 + h * 64 + (r - 128)
                               : 1536 + h;
            }
            dst[(size_t)nd * K + k0 + tx] = __float2half(tile[tx][i]);
        }
    }
}

// ---------------- LayerNorm ----------------
__global__ __launch_bounds__(256)
void ln_kernel(const float* __restrict__ x, const float* __restrict__ gamma,
               const float* __restrict__ beta)
{
    const int w = threadIdx.x >> 5, lane = threadIdx.x & 31;
    const int r = blockIdx.x * 8 + w;
    const float* xr = x + (size_t)r * INDIM;

    float4 v[4];
    float s = 0.f, ss = 0.f;
    #pragma unroll
    for (int i = 0; i < 4; i++) {
        v[i] = *(const float4*)(xr + lane * 4 + i * 128);
        s  += v[i].x + v[i].y + v[i].z + v[i].w;
        ss += v[i].x * v[i].x + v[i].y * v[i].y + v[i].z * v[i].z + v[i].w * v[i].w;
    }
    #pragma unroll
    for (int o = 16; o; o >>= 1) {
        s  += __shfl_xor_sync(~0u, s, o);
        ss += __shfl_xor_sync(~0u, ss, o);
    }
    const float mu = s * (1.f / INDIM);
    const float inv = rsqrtf(ss * (1.f / INDIM) - mu * mu + LN_EPS);

    __half* hr = g_hh + (size_t)r * INDIM;
    #pragma unroll
    for (int i = 0; i < 4; i++) {
        const int c0 = lane * 4 + i * 128;
        const float4 gm = *(const float4*)(gamma + c0);
        const float4 bt = *(const float4*)(beta + c0);
        __half2 h0 = __floats2half2_rn((v[i].x - mu) * inv * gm.x + bt.x,
                                       (v[i].y - mu) * inv * gm.y + bt.y);
        __half2 h1 = __floats2half2_rn((v[i].z - mu) * inv * gm.z + bt.z,
                                       (v[i].w - mu) * inv * gm.w + bt.w);
        *(uint2*)(hr + c0) = make_uint2(*(uint32_t*)&h0, *(uint32_t*)&h1);
    }
}

// ---------------- big GEMM (unchanged; occ 2, 128-reg budget) ----------------
#define BK 32
#define KT (INDIM / BK)
#define ROWP 40
#define STG (128 * ROWP)
#define GEMM_SMEM (3 * 2 * STG * 2)

__device__ __forceinline__ void load_stage(__half* sm, const __half* __restrict__ g,
                                           int row0, int k0, int tid)
{
    #pragma unroll
    for (int i = 0; i < 2; i++) {
        const int idx = tid + i * 256;
        const int row = idx >> 2, ch = (idx & 3) << 3;
        uint32_t dst;
        asm("{ .reg .u64 t; cvta.to.shared.u64 t, %1; cvt.u32.u64 %0, t; }"
            : "=r"(dst) : "l"(sm + row * ROWP + ch));
        asm volatile("cp.async.cg.shared.global [%0], [%1], 16;"
                     :: "r"(dst), "l"(g + (size_t)(row0 + row) * INDIM + (k0 + ch)));
    }
}

__global__ __launch_bounds__(256, 2)
void gemm_hmma_kernel(const __half* __restrict__ A, const __half* __restrict__ Bt,
                      float* __restrict__ C, __half* __restrict__ Ch,
                      const float* __restrict__ Res, int Ncols)
{
    extern __shared__ __half sm[];
    const uint32_t smb = smem_u32(sm);
    const int tid = threadIdx.x, wid = tid >> 5, lane = tid & 31;
    const int bm = blockIdx.y * 128, bn = blockIdx.x * 128;
    const int wm = (wid >> 2) * 64, wn = (wid & 3) * 32;
    const int g = lane >> 2, c = lane & 3;
    const int rA = (lane & 7) + ((lane >> 3) & 1) * 8;
    const int cA = ((lane >> 4) & 1) * 8;
    const int rB = (lane & 7) + ((lane >> 4) & 1) * 8;
    const int cB = ((lane >> 3) & 1) * 8;

    float acc[4][4][4];
    #pragma unroll
    for (int i = 0; i < 4; i++)
        #pragma unroll
        for (int j = 0; j < 4; j++)
            #pragma unroll
            for (int r = 0; r < 4; r++) acc[i][j][r] = 0.f;

    load_stage(sm, A, bm, 0, tid); load_stage(sm + 3 * STG, Bt, bn, 0, tid); CP_COMMIT();
    load_stage(sm + STG, A, bm, BK, tid); load_stage(sm + 4 * STG, Bt, bn, BK, tid); CP_COMMIT();

    for (int kt = 0; kt < KT; ++kt) {
        CP_WAIT(1);
        __syncthreads();
        if (kt + 2 < KT) {
            const int ps = (kt + 2) % 3;
            load_stage(sm + ps * STG, A, bm, (kt + 2) * BK, tid);
            load_stage(sm + (3 + ps) * STG, Bt, bn, (kt + 2) * BK, tid);
        }
        CP_COMMIT();
        const uint32_t sau = smb + ((kt % 3) * STG) * 2;
        const uint32_t sbu = smb + ((3 + kt % 3) * STG) * 2;
        #pragma unroll
        for (int ks = 0; ks < 2; ks++) {
            const int kb = ks * 16;
            uint32_t af[4][4], bf[4][2];
            #pragma unroll
            for (int im = 0; im < 4; im++)
                LDSM4(af[im][0], af[im][1], af[im][2], af[im][3],
                      sau + ((wm + im * 16 + rA) * ROWP + kb + cA) * 2);
            #pragma unroll
            for (int i2 = 0; i2 < 2; i2++)
                LDSM4(bf[2 * i2][0], bf[2 * i2][1], bf[2 * i2 + 1][0], bf[2 * i2 + 1][1],
                      sbu + ((wn + i2 * 16 + rB) * ROWP + kb + cB) * 2);
            #pragma unroll
            for (int im = 0; im < 4; im++)
                #pragma unroll
                for (int in = 0; in < 4; in++)
                    MMA16816(acc[im][in], af[im][0], af[im][1], af[im][2], af[im][3],
                             bf[in][0], bf[in][1]);
        }
    }

    #pragma unroll
    for (int im = 0; im < 4; im++)
        #pragma unroll
        for (int in = 0; in < 4; in++) {
            const int col = bn + wn + in * 8 + 2 * c;
            if (col < Ncols) {
                const int r0 = bm + wm + im * 16 + g;
                if (Ch) {
                    *(__half2*)&Ch[(size_t)r0 * Ncols + col] =
                        __floats2half2_rn(acc[im][in][0], acc[im][in][1]);
                    *(__half2*)&Ch[(size_t)(r0 + 8) * Ncols + col] =
                        __floats2half2_rn(acc[im][in][2], acc[im][in][3]);
                } else {
                    float2 v0 = make_float2(acc[im][in][0], acc[im][in][1]);
                    float2 v1 = make_float2(acc[im][in][2], acc[im][in][3]);
                    const float2 a0 = *(const float2*)(Res + (size_t)r0 * Ncols + col);
                    const float2 a1 = *(const float2*)(Res + (size_t)(r0 + 8) * Ncols + col);
                    v0.x += a0.x; v0.y += a0.y; v1.x += a1.x; v1.y += a1.y;
                    *(float2*)(C + (size_t)r0 * Ncols + col) = v0;
                    *(float2*)(C + (size_t)(r0 + 8) * Ncols + col) = v1;
                }
            }
        }
}

// ---------------- fused scan: 4 barriers/chunk, vectorized solve ----------------
// Tiles: sKb[2] | sQ | sV->P | sU | sG->Ostage | sS | sWh
#define FUSED_SMEM (8 * TILE_H * 2 + (64 * PADF + 64 * 68 + 64) * 4)

__device__ __forceinline__ void act_phase(__half* sKd, __half* sQ, __half* sV, float* sbt,
    const uint4& pq0, const uint4& pq1, const uint4& pk0, const uint4& pk1,
    const uint4& pv0, const uint4& pv1, float pbeta, int tt, int qt)
{
    if (qt == 0) sbt[tt] = 1.f / (1.f + __expf(-pbeta));
    __half hq[16], hk[16];
    *(uint4*)&hq[0] = pq0; *(uint4*)&hq[8] = pq1;
    *(uint4*)&hk[0] = pk0; *(uint4*)&hk[8] = pk1;
    float qv[16], kv[16];
    float sq = 0.f, sk_ = 0.f;
    #pragma unroll
    for (int i = 0; i < 16; i++) {
        float xq = __half2float(hq[i]);
        float xk = __half2float(hk[i]);
        qv[i] = xq > 0.f ? xq + 1.f : __expf(xq);
        kv[i] = xk > 0.f ? xk + 1.f : __expf(xk);
        sq += qv[i]; sk_ += kv[i];
    }
    sq  += __shfl_xor_sync(~0u, sq, 1);  sq  += __shfl_xor_sync(~0u, sq, 2);
    sk_ += __shfl_xor_sync(~0u, sk_, 1); sk_ += __shfl_xor_sync(~0u, sk_, 2);
    const float iq = 1.f / sq, ik = 1.f / sk_;
    __half outq[16], outk[16];
    #pragma unroll
    for (int i = 0; i < 16; i++) {
        outq[i] = __float2half(qv[i] * iq);
        outk[i] = __float2half(kv[i] * ik);
    }
    const int cb = qt * 16;
    *(uint4*)&sQ[tt * PADH + cb]      = *(uint4*)&outq[0];
    *(uint4*)&sQ[tt * PADH + cb + 8]  = *(uint4*)&outq[8];
    *(uint4*)&sKd[tt * PADH + cb]     = *(uint4*)&outk[0];
    *(uint4*)&sKd[tt * PADH + cb + 8] = *(uint4*)&outk[8];
    *(uint4*)&sV[tt * PADH + cb]      = pv0;
    *(uint4*)&sV[tt * PADH + cb + 8]  = pv1;
}

__global__ __launch_bounds__(256, 2)
void fused_scan_kernel()
{
    extern __shared__ char smraw[];
    __half* sKb[2] = { (__half*)smraw, (__half*)smraw + TILE_H };
    __half* sQ   = (__half*)smraw + 2 * TILE_H;
    __half* sV   = sQ  + TILE_H;
    __half* sU   = sV  + TILE_H;
    __half* sG   = sU  + TILE_H;
    __half* sS   = sG  + TILE_H;
    __half* sWh  = sS  + TILE_H;
    float*  sA   = (float*)(sWh + TILE_H);
    float*  sW   = sA + 64 * PADF;
    float*  sbt  = sW + 64 * 68;

    const int bh = blockIdx.x;
    const int b = bh >> 3, hh = bh & 7;
    const int tid = threadIdx.x, wid = tid >> 5, lane = tid & 31;
    const int g = lane >> 2, cq = lane & 3;
    const int tt = tid >> 2, qt = tid & 3;
    const int m0 = (wid & 3) * 16, n0 = (wid >> 2) * 32;
    const int seg = hh * 64 + qt * 16;

    #pragma unroll
    for (int i = 0; i < 16; i++) {
        const int e = tid * 16 + i;
        const int r = e >> 6, c2 = e & 63;
        sW[r * 68 + c2] = 0.f;
        sWh[r * PADH + c2] = __float2half(0.f);
    }

    uint4 pq0, pq1, pk0, pk1, pv0, pv1;
    float pbeta = 0.f;
    {   // prefetch + act chunk 0, then prefetch chunk 1
        const __half* rowp = g_qkvbh + (size_t)(tt * BSZ + b) * NQKVB_PAD;
        pq0 = *(const uint4*)(rowp + seg);        pq1 = *(const uint4*)(rowp + seg + 8);
        pk0 = *(const uint4*)(rowp + 512 + seg);  pk1 = *(const uint4*)(rowp + 512 + seg + 8);
        pv0 = *(const uint4*)(rowp + 1024 + seg); pv1 = *(const uint4*)(rowp + 1024 + seg + 8);
        if (qt == 0) pbeta = __half2float(rowp[1536 + hh]);
        act_phase(sKb[0], sQ, sV, sbt, pq0, pq1, pk0, pk1, pv0, pv1, pbeta, tt, qt);
        const __half* rn = g_qkvbh + (size_t)((64 + tt) * BSZ + b) * NQKVB_PAD;
        pq0 = *(const uint4*)(rn + seg);        pq1 = *(const uint4*)(rn + seg + 8);
        pk0 = *(const uint4*)(rn + 512 + seg);  pk1 = *(const uint4*)(rn + 512 + seg + 8);
        pv0 = *(const uint4*)(rn + 1024 + seg); pv1 = *(const uint4*)(rn + 1024 + seg + 8);
        if (qt == 0) pbeta = __half2float(rn[1536 + hh]);
    }
    __syncthreads();

    for (int cch = 0; cch < NC; cch++) {
        const int t0 = cch * 64;
        const int cur = cch & 1, nxt = cur ^ 1;
        __half* sK = sKb[cur];

        // ---- (b) A = K·K^T, S = Q·K^T ----
        {
            float aA[16], aS[16];
            #pragma unroll
            for (int i = 0; i < 16; i++) { aA[i] = 0.f; aS[i] = 0.f; }
            wgemmT<0, 0>(sK, sK, aA, m0, n0, lane);
            wgemmT<0, 0>(sQ, sK, aS, m0, n0, lane);
            #pragma unroll
            for (int nf = 0; nf < 4; nf++)
                #pragma unroll
                for (int qq = 0; qq < 2; qq++) {
                    const int t = m0 + g + qq * 8;
                    const int s0 = n0 + nf * 8 + 2 * cq;
                    sA[t * PADF + s0]     = (s0 < t)     ? sbt[t] * aA[nf * 4 + qq * 2]     : 0.f;
                    sA[t * PADF + s0 + 1] = (s0 + 1 < t) ? sbt[t] * aA[nf * 4 + qq * 2 + 1] : 0.f;
                    const float s0v = (s0 <= t)     ? aS[nf * 4 + qq * 2]     : 0.f;
                    const float s1v = (s0 + 1 <= t) ? aS[nf * 4 + qq * 2 + 1] : 0.f;
                    *(__half2*)&sS[t * PADH + s0] = __floats2half2_rn(s0v, s1v);
                }
        }
        __syncthreads();   // (b)

        // ---- (c) kw = K·W^T, O1 = Q·W^T, P = V − kw; solve → G ----
        float oa[16];
        {
            float akw[16];
            #pragma unroll
            for (int i = 0; i < 16; i++) { akw[i] = 0.f; oa[i] = 0.f; }
            wgemmT<0, 0>(sK, sWh, akw, m0, n0, lane);
            wgemmT<0, 0>(sQ, sWh, oa, m0, n0, lane);
            #pragma unroll
            for (int nf = 0; nf < 4; nf++)
                #pragma unroll
                for (int qq = 0; qq < 2; qq++) {
                    const int t = m0 + g + qq * 8;
                    const int s0 = n0 + nf * 8 + 2 * cq;
                    const __half2 vv = *(const __half2*)&sV[t * PADH + s0];
                    *(__half2*)&sV[t * PADH + s0] = __floats2half2_rn(
                        __half2float(vv.x) - akw[nf * 4 + qq * 2],
                        __half2float(vv.y) - akw[nf * 4 + qq * 2 + 1]);
                }
        }
        {
            const int col = tid >> 2, qr = tid & 3;
            float m[16];
            #pragma unroll
            for (int i = 0; i < 16; i++) m[i] = (16 * qr + i == col) ? 1.f : 0.f;
            #pragma unroll
            for (int p = 0; p < 4; p++) {
                const bool live = (16 * p + 15 >= col);
                if (qr == p && live) {
                    // row-oriented in-block forward substitution
                    #pragma unroll
                    for (int i = 1; i < 16; i++) {
                        const float* ar = &sA[(16 * p + i) * PADF + 16 * p];
                        float acc = m[i];
                        #pragma unroll
                        for (int s = 0; s < 15; s++)
                            if (s < i) acc -= ar[s] * m[s];
                        m[i] = acc;
                    }
                }
                float ms[16];
                #pragma unroll
                for (int si = 0; si < 16; si++) ms[si] = __shfl_sync(~0u, m[si], p, 4);
                if (qr > p && live) {
                    #pragma unroll
                    for (int i = 0; i < 16; i++) {
                        const float* ar = &sA[(16 * qr + i) * PADF + 16 * p];
                        const float4 a0 = *(const float4*)ar;
                        const float4 a1 = *(const float4*)(ar + 4);
                        const float4 a2 = *(const float4*)(ar + 8);
                        const float4 a3 = *(const float4*)(ar + 12);
                        float acc = m[i];
                        acc -= a0.x * ms[0];  acc -= a0.y * ms[1];
                        acc -= a0.z * ms[2];  acc -= a0.w * ms[3];
                        acc -= a1.x * ms[4];  acc -= a1.y * ms[5];
                        acc -= a1.z * ms[6];  acc -= a1.w * ms[7];
                        acc -= a2.x * ms[8];  acc -= a2.y * ms[9];
                        acc -= a2.z * ms[10]; acc -= a2.w * ms[11];
                        acc -= a3.x * ms[12]; acc -= a3.y * ms[13];
                        acc -= a3.z * ms[14]; acc -= a3.w * ms[15];
                        m[i] = acc;
                    }
                }
            }
            const float bc = sbt[col];
            #pragma unroll
            for (int i = 0; i < 16; i++)
                sG[(16 * qr + i) * PADH + col] = __float2half(m[i] * bc);
        }
        __syncthreads();   // (c)

        // ---- (d) U = G @ P ----
        {
            float aU[16];
            #pragma unroll
            for (int i = 0; i < 16; i++) aU[i] = 0.f;
            wgemmT<0, 1>(sG, sV, aU, m0, n0, lane);
            #pragma unroll
            for (int nf = 0; nf < 4; nf++)
                #pragma unroll
                for (int qq = 0; qq < 2; qq++) {
                    const int t = m0 + g + qq * 8;
                    const int col = n0 + nf * 8 + 2 * cq;
                    *(__half2*)&sU[t * PADH + col] =
                        __floats2half2_rn(aU[nf * 4 + qq * 2], aU[nf * 4 + qq * 2 + 1]);
                }
        }
        __syncthreads();   // (d)

        // ---- (e) O2 = S@U (stage in sG); W += U^T@K; act(c+1) ----
        wgemmT<0, 1>(sS, sU, oa, m0, n0, lane);
        #pragma unroll
        for (int nf = 0; nf < 4; nf++)
            #pragma unroll
            for (int qq = 0; qq < 2; qq++) {
                const int t = m0 + g + qq * 8;
                const int col = n0 + nf * 8 + 2 * cq;
                *(__half2*)&sG[t * PADH + col] =
                    __floats2half2_rn(oa[nf * 4 + qq * 2], oa[nf * 4 + qq * 2 + 1]);
            }
        {
            float wa[16];
            #pragma unroll
            for (int i = 0; i < 16; i++) wa[i] = 0.f;
            wgemmT<1, 1>(sU, sK, wa, m0, n0, lane);
            #pragma unroll
            for (int nf = 0; nf < 4; nf++)
                #pragma unroll
                for (int qq = 0; qq < 2; qq++) {
                    const int i = m0 + g + qq * 8;
                    const int j0 = n0 + nf * 8 + 2 * cq;
                    const float w0 = sW[i * 68 + j0]     + wa[nf * 4 + qq * 2];
                    const float w1 = sW[i * 68 + j0 + 1] + wa[nf * 4 + qq * 2 + 1];
                    *(float2*)&sW[i * 68 + j0] = make_float2(w0, w1);
                    *(__half2*)&sWh[i * PADH + j0] = __floats2half2_rn(w0, w1);
                }
        }
        if (cch + 1 < NC)
            act_phase(sKb[nxt], sQ, sV, sbt, pq0, pq1, pk0, pk1, pv0, pv1, pbeta, tt, qt);
        __syncthreads();   // (e)

        // ---- tail: coalesced O store; prefetch chunk c+2 ----
        {
            const int qseg = qt * 16;
            const uint4* src = (const uint4*)&sG[tt * PADH + qseg];
            uint4* dst = (uint4*)&g_oh[(size_t)((t0 + tt) * BSZ + b) * INDIM + hh * 64 + qseg];
            dst[0] = src[0];
            dst[1] = src[1];
        }
        if (cch + 2 < NC) {
            const __half* rn = g_qkvbh + (size_t)(((cch + 2) * 64 + tt) * BSZ + b) * NQKVB_PAD;
            pq0 = *(const uint4*)(rn + seg);        pq1 = *(const uint4*)(rn + seg + 8);
            pk0 = *(const uint4*)(rn + 512 + seg);  pk1 = *(const uint4*)(rn + 512 + seg + 8);
            pv0 = *(const uint4*)(rn + 1024 + seg); pv1 = *(const uint4*)(rn + 1024 + seg + 8);
            if (qt == 0) pbeta = __half2float(rn[1536 + hh]);
        }
    }
}

// ---------------- launch ----------------
extern "C" void kernel_launch(void* const* d_in, const int* in_sizes, int n_in,
                              void* d_out, int out_size)
{
    const float* x      = (const float*)d_in[0];
    const float* gamma  = (const float*)d_in[1];
    const float* beta   = (const float*)d_in[2];
    const float* w_slow = (const float*)d_in[3];
    const float* w_out  = (const float*)d_in[4];
    float* out = (float*)d_out;

    static bool attr_set = false;
    if (!attr_set) {
        cudaFuncSetAttribute(gemm_hmma_kernel, cudaFuncAttributeMaxDynamicSharedMemorySize, GEMM_SMEM);
        cudaFuncSetAttribute(fused_scan_kernel, cudaFuncAttributeMaxDynamicSharedMemorySize, FUSED_SMEM);
        attr_set = true;
    }

    __half* wslowT; cudaGetSymbolAddress((void**)&wslowT, g_wslowT);
    __half* woutT;  cudaGetSymbolAddress((void**)&woutT,  g_woutT);
    __half* hbuf;   cudaGetSymbolAddress((void**)&hbuf,   g_hh);
    __half* qkvbh;  cudaGetSymbolAddress((void**)&qkvbh,  g_qkvbh);
    __half* obuf;   cudaGetSymbolAddress((void**)&obuf,   g_oh);

    {
        dim3 blk(256);
        dim3 g1(NQKVB_PAD / 32, INDIM / 32);
        transpose_pad_kernel<<<g1, blk>>>(w_slow, wslowT, INDIM, NQKVB, NQKVB_PAD, 1);
        dim3 g2(INDIM / 32, INDIM / 32);
        transpose_pad_kernel<<<g2, blk>>>(w_out, woutT, INDIM, INDIM, INDIM, 0);
    }
    ln_kernel<<<MROWS / 8, 256>>>(x, gamma, beta);
    {
        dim3 grid(NQKVB_PAD / 128, MROWS / 128);
        gemm_hmma_kernel<<<grid, 256, GEMM_SMEM>>>(hbuf, wslowT, nullptr, qkvbh, nullptr, NQKVB_PAD);
    }
    fused_scan_kernel<<<NBH, 256, FUSED_SMEM>>>();
    {
        dim3 grid(INDIM / 128, MROWS / 128);
        gemm_hmma_kernel<<<grid, 256, GEMM_SMEM>>>(obuf, woutT, out, nullptr, x, INDIM);
    }
}